// round 4
// baseline (speedup 1.0000x reference)
#include <cuda_runtime.h>
#include <cuda_fp16.h>
#include <cstdint>

#define C    512
#define SP   4096
#define NH   8
#define HD   64
#define NB   2
// fold softmax scale and log2(e) into Q projection; softmax uses exp2
#define QS   (0.125f * 1.44269504088896f)

// fp16 scratch (allocation-free rule: __device__ globals)
__device__ __half g_xh [NB * SP * C];          // x transposed: [n][s][c]
__device__ __half g_Wh [4 * C * C];            // Wq(scaled),Wk,Wv,Wo as [o][c]
__device__ __half g_Qh [NB * NH * SP * HD];    // [nh][s][d] (scaled)
__device__ __half g_Kh [NB * NH * SP * HD];    // [nh][s][d]
__device__ __half g_Vh [NB * NH * HD * SP];    // [nh][d][s]
__device__ __half g_AOh[NB * NH * SP * HD];    // [nh][s][d]

// ---------------------------------------------------------------- helpers
__device__ __forceinline__ uint32_t cvta_s(const void* p) {
    return (uint32_t)__cvta_generic_to_shared(p);
}
__device__ __forceinline__ void cp16(uint32_t s, const void* g) {
    asm volatile("cp.async.cg.shared.global [%0], [%1], 16;\n" ::"r"(s), "l"(g));
}
#define CP_COMMIT asm volatile("cp.async.commit_group;\n" ::)
#define CP_WAIT(n) asm volatile("cp.async.wait_group %0;\n" ::"n"(n))

__device__ __forceinline__ void ldsm4(uint32_t a[4], uint32_t addr) {
    asm volatile("ldmatrix.sync.aligned.m8n8.x4.shared.b16 {%0,%1,%2,%3}, [%4];"
                 : "=r"(a[0]), "=r"(a[1]), "=r"(a[2]), "=r"(a[3]) : "r"(addr));
}
__device__ __forceinline__ void ldsm2(uint32_t& a0, uint32_t& a1, uint32_t addr) {
    asm volatile("ldmatrix.sync.aligned.m8n8.x2.shared.b16 {%0,%1}, [%2];"
                 : "=r"(a0), "=r"(a1) : "r"(addr));
}
// D += A * B, fp16 in, fp32 accum
__device__ __forceinline__ void mma16816(float c[4], const uint32_t a[4],
                                         uint32_t b0, uint32_t b1) {
    asm volatile(
        "mma.sync.aligned.m16n8k16.row.col.f32.f16.f16.f32 "
        "{%0,%1,%2,%3},{%4,%5,%6,%7},{%8,%9},{%0,%1,%2,%3};"
        : "+f"(c[0]), "+f"(c[1]), "+f"(c[2]), "+f"(c[3])
        : "r"(a[0]), "r"(a[1]), "r"(a[2]), "r"(a[3]), "r"(b0), "r"(b1));
}
// one formula for A-frags and Bt-frags: base(bytes), r0/c0/stride in halves
__device__ __forceinline__ uint32_t lds_addr(uint32_t base, int r0, int c0, int stride) {
    int lane = threadIdx.x & 31;
    return base + (uint32_t)(((r0 + (lane & 15)) * stride + c0 + ((lane >> 4) << 3)) * 2);
}
__device__ __forceinline__ float ex2f(float x) {
    float y; asm("ex2.approx.ftz.f32 %0, %1;" : "=f"(y) : "f"(x)); return y;
}
// pack two fp32 into half2 {lo, hi}
__device__ __forceinline__ uint32_t cvt2h(float lo, float hi) {
    uint32_t r; asm("cvt.rn.f16x2.f32 %0, %1, %2;" : "=r"(r) : "f"(hi), "f"(lo));
    return r;
}
__device__ __forceinline__ uint32_t hsub2u(uint32_t a, uint32_t b) {
    uint32_t r; asm("sub.f16x2 %0, %1, %2;" : "=r"(r) : "r"(a), "r"(b)); return r;
}
__device__ __forceinline__ uint32_t hmul2u(uint32_t a, uint32_t b) {
    uint32_t r; asm("mul.f16x2 %0, %1, %2;" : "=r"(r) : "r"(a), "r"(b)); return r;
}
__device__ __forceinline__ uint32_t ex2h2(uint32_t a) {
    uint32_t r; asm("ex2.approx.f16x2 %0, %1;" : "=r"(r) : "r"(a)); return r;
}

// ---------------------------------------------------------------- converts
__global__ __launch_bounds__(256) void convert_w_kernel(
    const float* __restrict__ Wq, const float* __restrict__ Wk,
    const float* __restrict__ Wv, const float* __restrict__ Wo)
{
    int i = blockIdx.x * 256 + threadIdx.x;          // 4*C*C total
    int which = i >> 18;                              // C*C = 2^18
    int j = i & (C * C - 1);
    const float* src = (which == 0) ? Wq : (which == 1) ? Wk : (which == 2) ? Wv : Wo;
    float v = src[j] * (which == 0 ? QS : 1.0f);
    g_Wh[i] = __float2half_rn(v);
}

__global__ __launch_bounds__(256) void transpose_x_kernel(const float* __restrict__ x)
{
    __shared__ float t[32][33];
    int n = blockIdx.z, s0 = blockIdx.x * 32, c0 = blockIdx.y * 32;
#pragma unroll
    for (int k = 0; k < 4; k++) {
        int idx = threadIdx.x + k * 256;
        int c = idx >> 5, s = idx & 31;
        t[c][s] = x[((size_t)n * C + c0 + c) * SP + s0 + s];
    }
    __syncthreads();
#pragma unroll
    for (int k = 0; k < 4; k++) {
        int idx = threadIdx.x + k * 256;
        int s = idx >> 5, c = idx & 31;
        g_xh[((size_t)n * SP + s0 + s) * C + c0 + c] = __float2half_rn(t[c][s]);
    }
}

// ---------------------------------------------------------------- QKV proj
// Out[s][o] = sum_c xT[s][c] * W[o][c];  BM=256(s) BN=64(o) BK=32
__global__ __launch_bounds__(256, 2) void proj_qkv_kernel(
    const float* __restrict__ bq, const float* __restrict__ bk,
    const float* __restrict__ bv)
{
    extern __shared__ __half sm[];
    __half* As[2] = { sm, sm + 256 * 40 };
    __half* Bs[2] = { sm + 2 * 256 * 40, sm + 2 * 256 * 40 + 64 * 40 };

    const int which = blockIdx.z % 3, n = blockIdx.z / 3;
    const int s0 = blockIdx.x * 256, o0 = blockIdx.y * 64;
    const int tid = threadIdx.x, w = tid >> 5, lane = tid & 31;

    const __half* Ag = g_xh + ((size_t)n * SP + s0) * C;
    const __half* Bg = g_Wh + (size_t)which * C * C + (size_t)o0 * C;

    float acc[2][8][4];
#pragma unroll
    for (int a = 0; a < 2; a++)
#pragma unroll
        for (int b = 0; b < 8; b++)
#pragma unroll
            for (int c = 0; c < 4; c++) acc[a][b][c] = 0.f;

    auto load_tiles = [&](int buf, int c0) {
        const __half* ga = Ag + (size_t)tid * C + c0;
        uint32_t sa = cvta_s(As[buf] + tid * 40);
        cp16(sa, ga); cp16(sa + 16, ga + 8); cp16(sa + 32, ga + 16); cp16(sa + 48, ga + 24);
        int r = tid >> 2, ch = tid & 3;
        cp16(cvta_s(Bs[buf] + r * 40 + ch * 8), Bg + (size_t)r * C + c0 + ch * 8);
    };

    load_tiles(0, 0);
    CP_COMMIT;
    int buf = 0;
    for (int kb = 0; kb < 16; kb++) {
        if (kb < 15) { load_tiles(buf ^ 1, (kb + 1) * 32); CP_COMMIT; }
        if (kb < 15) CP_WAIT(1); else CP_WAIT(0);
        __syncthreads();
        uint32_t ab = cvta_s(As[buf]), bb = cvta_s(Bs[buf]);
#pragma unroll
        for (int ks = 0; ks < 2; ks++) {
            uint32_t Af[2][4], Bf[4][4];
#pragma unroll
            for (int mt = 0; mt < 2; mt++)
                ldsm4(Af[mt], lds_addr(ab, w * 32 + mt * 16, ks * 16, 40));
#pragma unroll
            for (int nt = 0; nt < 4; nt++)
                ldsm4(Bf[nt], lds_addr(bb, nt * 16, ks * 16, 40));
#pragma unroll
            for (int mt = 0; mt < 2; mt++)
#pragma unroll
                for (int nt = 0; nt < 4; nt++) {
                    mma16816(acc[mt][2 * nt],     Af[mt], Bf[nt][0], Bf[nt][2]);
                    mma16816(acc[mt][2 * nt + 1], Af[mt], Bf[nt][1], Bf[nt][3]);
                }
        }
        __syncthreads();
        buf ^= 1;
    }

    const float* bias = (which == 0) ? bq : (which == 1) ? bk : bv;
    const float bsc = (which == 0) ? QS : 1.0f;
    const int h = o0 >> 6;
    __half* outQK = (which == 0) ? g_Qh : g_Kh;
#pragma unroll
    for (int mt = 0; mt < 2; mt++)
#pragma unroll
        for (int f = 0; f < 8; f++) {
            int srow = s0 + w * 32 + mt * 16 + (lane >> 2);
            int o = o0 + f * 8 + (lane & 3) * 2;
            int d = o & 63;
            float b0 = bias[o] * bsc, b1 = bias[o + 1] * bsc;
            float v00 = acc[mt][f][0] + b0, v01 = acc[mt][f][1] + b1;
            float v10 = acc[mt][f][2] + b0, v11 = acc[mt][f][3] + b1;
            if (which < 2) {
                size_t base = ((size_t)(n * NH + h) * SP + srow) * 64 + d;
                *(__half2*)(outQK + base)            = __floats2half2_rn(v00, v01);
                *(__half2*)(outQK + base + 8 * 64)   = __floats2half2_rn(v10, v11);
            } else {
                size_t base = ((size_t)(n * NH + h) * 64 + d) * SP + srow;
                g_Vh[base]          = __float2half_rn(v00);
                g_Vh[base + SP]     = __float2half_rn(v01);
                g_Vh[base + 8]      = __float2half_rn(v10);
                g_Vh[base + SP + 8] = __float2half_rn(v11);
            }
        }
}

// ---------------------------------------------------------------- attention
// CTA: 128 q-rows of one (n,h); 8 warps x 16 rows; 128-key iterations.
// smem: Qs[128][72], Ks[2][128 keys][72 d], Vs[2][72 d][136 keys]
// V rows 64-71 hold a constant ones-column tile so GEMM2 accumulates the
// softmax row sum l into a 9th fp32 O fragment (exact, auto-rescaled).
__global__ __launch_bounds__(256, 2) void attn_kernel()
{
    extern __shared__ __half sm[];
    __half* Qs    = sm;                                        // 128*72
    __half* Ks[2] = { sm + 9216,  sm + 9216 + 9216 };          // 128*72 each
    __half* Vs[2] = { sm + 27648, sm + 27648 + 9792 };         // 72*136 each

    const int tid = threadIdx.x, w = tid >> 5, lane = tid & 31;
    const int nh = blockIdx.y;
    const int q0 = blockIdx.x * 128;
    const __half* Qg = g_Qh + ((size_t)nh * SP + q0) * 64;
    const __half* Kg = g_Kh + (size_t)nh * SP * 64;
    const __half* Vg = g_Vh + (size_t)nh * 64 * SP;

    // Q: 128 rows x 8 chunks
#pragma unroll
    for (int i = 0; i < 4; i++) {
        int idx = tid + i * 256, r = idx >> 3, ch = idx & 7;
        cp16(cvta_s(Qs + r * 72 + ch * 8), Qg + (size_t)r * 64 + ch * 8);
    }
    CP_COMMIT;

    auto load_kv = [&](int buf, int t0) {
#pragma unroll
        for (int i = 0; i < 4; i++) {
            int idx = tid + i * 256;
            int kr = idx >> 3, kch = idx & 7;            // K: 128 rows x 8 chunks
            cp16(cvta_s(Ks[buf] + kr * 72 + kch * 8),
                 Kg + ((size_t)(t0 + kr)) * 64 + kch * 8);
            int vr = idx >> 4, vch = idx & 15;           // V: 64 rows x 16 chunks
            cp16(cvta_s(Vs[buf] + vr * 136 + vch * 8),
                 Vg + (size_t)vr * SP + t0 + vch * 8);
        }
    };
    load_kv(0, 0);
    CP_COMMIT;

    // init ones-column rows (d'=64 -> 1.0, d'=65..71 -> 0) in both V buffers
    for (int idx = tid; idx < 8 * 136; idx += 256) {
        int r = 64 + idx / 136, cc = idx % 136;
        __half v = (r == 64) ? __float2half_rn(1.0f) : __float2half_rn(0.0f);
        Vs[0][r * 136 + cc] = v;
        Vs[1][r * 136 + cc] = v;
    }
    __syncthreads();

    // constant ones B-frag (valid for every kt: values independent of key col)
    uint32_t ones0, ones1;
    {
        uint32_t addr = cvta_s(Vs[0]) +
            (uint32_t)(((64 + (lane & 7)) * 136 + ((lane >> 3) & 1) * 8) * 2);
        ldsm2(ones0, ones1, addr);
    }

    float O[9][4];
#pragma unroll
    for (int f = 0; f < 9; f++)
#pragma unroll
        for (int e = 0; e < 4; e++) O[f][e] = 0.f;
    float m0 = -1e30f, m1 = -1e30f;
    uint32_t Qa[4][4];

    int buf = 0;
    for (int it = 0; it < SP / 128; it++) {
        if (it < SP / 128 - 1) { load_kv(buf ^ 1, (it + 1) * 128); CP_COMMIT; }
        if (it < SP / 128 - 1) CP_WAIT(1); else CP_WAIT(0);
        __syncthreads();
        if (it == 0) {
            uint32_t qb = cvta_s(Qs);
#pragma unroll
            for (int ks = 0; ks < 4; ks++)
                ldsm4(Qa[ks], lds_addr(qb, w * 16, ks * 16, 72));
        }
        uint32_t kb = cvta_s(Ks[buf]);
        uint32_t vb = cvta_s(Vs[buf]);

        uint32_t P0[4][4], P1[4][4];
        float mc0, mc1, mn0, mn1;

        // ---- chunk 0: keys 0-63 of tile ----
        {
            float S[8][4];
#pragma unroll
            for (int f = 0; f < 8; f++)
#pragma unroll
                for (int e = 0; e < 4; e++) S[f][e] = 0.f;
#pragma unroll
            for (int ks = 0; ks < 4; ks++) {
                uint32_t Bf[4][4];
#pragma unroll
                for (int nt = 0; nt < 4; nt++)
                    ldsm4(Bf[nt], lds_addr(kb, nt * 16, ks * 16, 72));
#pragma unroll
                for (int nt = 0; nt < 4; nt++) {
                    mma16816(S[2 * nt],     Qa[ks], Bf[nt][0], Bf[nt][2]);
                    mma16816(S[2 * nt + 1], Qa[ks], Bf[nt][1], Bf[nt][3]);
                }
            }
            float rm0 = S[0][0], rm1 = S[0][2];
#pragma unroll
            for (int f = 0; f < 8; f++) {
                rm0 = fmaxf(rm0, fmaxf(S[f][0], S[f][1]));
                rm1 = fmaxf(rm1, fmaxf(S[f][2], S[f][3]));
            }
            rm0 = fmaxf(rm0, __shfl_xor_sync(0xffffffffu, rm0, 1));
            rm0 = fmaxf(rm0, __shfl_xor_sync(0xffffffffu, rm0, 2));
            rm1 = fmaxf(rm1, __shfl_xor_sync(0xffffffffu, rm1, 1));
            rm1 = fmaxf(rm1, __shfl_xor_sync(0xffffffffu, rm1, 2));
            mc0 = fmaxf(m0, rm0); mc1 = fmaxf(m1, rm1);
            uint32_t mh0 = cvt2h(mc0, mc0), mh1 = cvt2h(mc1, mc1);
#pragma unroll
            for (int kt = 0; kt < 4; kt++) {
                P0[kt][0] = ex2h2(hsub2u(cvt2h(S[2*kt][0],   S[2*kt][1]),   mh0));
                P0[kt][1] = ex2h2(hsub2u(cvt2h(S[2*kt][2],   S[2*kt][3]),   mh1));
                P0[kt][2] = ex2h2(hsub2u(cvt2h(S[2*kt+1][0], S[2*kt+1][1]), mh0));
                P0[kt][3] = ex2h2(hsub2u(cvt2h(S[2*kt+1][2], S[2*kt+1][3]), mh1));
            }
        }

        // ---- chunk 1: keys 64-127 of tile ----
        {
            float S[8][4];
#pragma unroll
            for (int f = 0; f < 8; f++)
#pragma unroll
                for (int e = 0; e < 4; e++) S[f][e] = 0.f;
#pragma unroll
            for (int ks = 0; ks < 4; ks++) {
                uint32_t Bf[4][4];
#pragma unroll
                for (int nt = 0; nt < 4; nt++)
                    ldsm4(Bf[nt], lds_addr(kb, 64 + nt * 16, ks * 16, 72));
#pragma unroll
                for (int nt = 0; nt < 4; nt++) {
                    mma16816(S[2 * nt],     Qa[ks], Bf[nt][0], Bf[nt][2]);
                    mma16816(S[2 * nt + 1], Qa[ks], Bf[nt][1], Bf[nt][3]);
                }
            }
            float rm0 = S[0][0], rm1 = S[0][2];
#pragma unroll
            for (int f = 0; f < 8; f++) {
                rm0 = fmaxf(rm0, fmaxf(S[f][0], S[f][1]));
                rm1 = fmaxf(rm1, fmaxf(S[f][2], S[f][3]));
            }
            rm0 = fmaxf(rm0, __shfl_xor_sync(0xffffffffu, rm0, 1));
            rm0 = fmaxf(rm0, __shfl_xor_sync(0xffffffffu, rm0, 2));
            rm1 = fmaxf(rm1, __shfl_xor_sync(0xffffffffu, rm1, 1));
            rm1 = fmaxf(rm1, __shfl_xor_sync(0xffffffffu, rm1, 2));
            mn0 = fmaxf(mc0, rm0); mn1 = fmaxf(mc1, rm1);
            uint32_t mh0 = cvt2h(mn0, mn0), mh1 = cvt2h(mn1, mn1);
#pragma unroll
            for (int kt = 0; kt < 4; kt++) {
                P1[kt][0] = ex2h2(hsub2u(cvt2h(S[2*kt][0],   S[2*kt][1]),   mh0));
                P1[kt][1] = ex2h2(hsub2u(cvt2h(S[2*kt][2],   S[2*kt][3]),   mh1));
                P1[kt][2] = ex2h2(hsub2u(cvt2h(S[2*kt+1][0], S[2*kt+1][1]), mh0));
                P1[kt][3] = ex2h2(hsub2u(cvt2h(S[2*kt+1][2], S[2*kt+1][3]), mh1));
            }
        }

        // correct P0 to the final max of this tile
        {
            float c0 = ex2f(mc0 - mn0), c1 = ex2f(mc1 - mn1);
            uint32_t ch0 = cvt2h(c0, c0), ch1 = cvt2h(c1, c1);
#pragma unroll
            for (int kt = 0; kt < 4; kt++) {
                P0[kt][0] = hmul2u(P0[kt][0], ch0);
                P0[kt][1] = hmul2u(P0[kt][1], ch1);
                P0[kt][2] = hmul2u(P0[kt][2], ch0);
                P0[kt][3] = hmul2u(P0[kt][3], ch1);
            }
        }
        // rescale O (l rides along in O[8])
        {
            float a0 = ex2f(m0 - mn0), a1 = ex2f(m1 - mn1);
            m0 = mn0; m1 = mn1;
#pragma unroll
            for (int f = 0; f < 9; f++) {
                O[f][0] *= a0; O[f][1] *= a0; O[f][2] *= a1; O[f][3] *= a1;
            }
        }

        // GEMM2: O[16q][64d (+l)] += P * V'
#pragma unroll
        for (int kt = 0; kt < 8; kt++) {
            const uint32_t* A = (kt < 4) ? P0[kt] : P1[kt - 4];
            uint32_t Bf[4][4];
#pragma unroll
            for (int nt = 0; nt < 4; nt++)
                ldsm4(Bf[nt], lds_addr(vb, nt * 16, kt * 16, 136));
#pragma unroll
            for (int nt = 0; nt < 4; nt++) {
                mma16816(O[2 * nt],     A, Bf[nt][0], Bf[nt][2]);
                mma16816(O[2 * nt + 1], A, Bf[nt][1], Bf[nt][3]);
            }
            mma16816(O[8], A, ones0, ones1);
        }
        __syncthreads();
        buf ^= 1;
    }

    // l lives in O[8][0] (row r) / O[8][2] (row r+8) of quad-leader lanes
    float l0 = __shfl_sync(0xffffffffu, O[8][0], lane & ~3);
    float l1 = __shfl_sync(0xffffffffu, O[8][2], lane & ~3);
    float inv0 = 1.0f / l0, inv1 = 1.0f / l1;
    int r = lane >> 2;
#pragma unroll
    for (int f = 0; f < 8; f++) {
        int d = f * 8 + (lane & 3) * 2;
        int q = q0 + w * 16 + r;
        size_t base = ((size_t)nh * SP + q) * 64 + d;
        *(__half2*)(g_AOh + base)          = __floats2half2_rn(O[f][0] * inv0, O[f][1] * inv0);
        *(__half2*)(g_AOh + base + 8 * 64) = __floats2half2_rn(O[f][2] * inv1, O[f][3] * inv1);
    }
}

// ---------------------------------------------------------------- out proj
__global__ __launch_bounds__(256, 2) void proj_out_kernel(
    const float* __restrict__ x, const float* __restrict__ bo,
    const float* __restrict__ gamma, float* __restrict__ out)
{
    extern __shared__ __half sm[];
    __half* As[2] = { sm, sm + 256 * 40 };
    __half* Bs[2] = { sm + 2 * 256 * 40, sm + 2 * 256 * 40 + 64 * 40 };

    const int n = blockIdx.z;
    const int s0 = blockIdx.x * 256, o0 = blockIdx.y * 64;
    const int tid = threadIdx.x, w = tid >> 5, lane = tid & 31;
    const __half* Bg = g_Wh + (size_t)3 * C * C + (size_t)o0 * C;

    float acc[2][8][4];
#pragma unroll
    for (int a = 0; a < 2; a++)
#pragma unroll
        for (int b = 0; b < 8; b++)
#pragma unroll
            for (int c = 0; c < 4; c++) acc[a][b][c] = 0.f;

    auto load_tiles = [&](int buf, int c0) {
        int hh = c0 >> 6, d0 = c0 & 63;
        const __half* ga = g_AOh + ((size_t)(n * NH + hh) * SP + s0 + tid) * 64 + d0;
        uint32_t sa = cvta_s(As[buf] + tid * 40);
        cp16(sa, ga); cp16(sa + 16, ga + 8); cp16(sa + 32, ga + 16); cp16(sa + 48, ga + 24);
        int r = tid >> 2, ch = tid & 3;
        cp16(cvta_s(Bs[buf] + r * 40 + ch * 8), Bg + (size_t)r * C + c0 + ch * 8);
    };

    load_tiles(0, 0);
    CP_COMMIT;
    int buf = 0;
    for (int kb = 0; kb < 16; kb++) {
        if (kb < 15) { load_tiles(buf ^ 1, (kb + 1) * 32); CP_COMMIT; }
        if (kb < 15) CP_WAIT(1); else CP_WAIT(0);
        __syncthreads();
        uint32_t ab = cvta_s(As[buf]), bb = cvta_s(Bs[buf]);
#pragma unroll
        for (int ks = 0; ks < 2; ks++) {
            uint32_t Af[2][4], Bf[4][4];
#pragma unroll
            for (int mt = 0; mt < 2; mt++)
                ldsm4(Af[mt], lds_addr(ab, w * 32 + mt * 16, ks * 16, 40));
#pragma unroll
            for (int nt = 0; nt < 4; nt++)
                ldsm4(Bf[nt], lds_addr(bb, nt * 16, ks * 16, 40));
#pragma unroll
            for (int mt = 0; mt < 2; mt++)
#pragma unroll
                for (int nt = 0; nt < 4; nt++) {
                    mma16816(acc[mt][2 * nt],     Af[mt], Bf[nt][0], Bf[nt][2]);
                    mma16816(acc[mt][2 * nt + 1], Af[mt], Bf[nt][1], Bf[nt][3]);
                }
        }
        __syncthreads();
        buf ^= 1;
    }

    const float g = gamma[0];
#pragma unroll
    for (int mt = 0; mt < 2; mt++)
#pragma unroll
        for (int f = 0; f < 8; f++) {
            int srow = s0 + w * 32 + mt * 16 + (lane >> 2);
            int o = o0 + f * 8 + (lane & 3) * 2;
            float b0 = bo[o], b1 = bo[o + 1];
            size_t p00 = ((size_t)n * C + o) * SP + srow;
            size_t p01 = p00 + SP;
            out[p00]     = g * (acc[mt][f][0] + b0) + x[p00];
            out[p01]     = g * (acc[mt][f][1] + b1) + x[p01];
            out[p00 + 8] = g * (acc[mt][f][2] + b0) + x[p00 + 8];
            out[p01 + 8] = g * (acc[mt][f][3] + b1) + x[p01 + 8];
        }
}

// ---------------------------------------------------------------- launch
extern "C" void kernel_launch(void* const* d_in, const int* in_sizes, int n_in,
                              void* d_out, int out_size)
{
    const float* x     = (const float*)d_in[0];
    const float* Wq    = (const float*)d_in[1];
    const float* bq    = (const float*)d_in[2];
    const float* Wk    = (const float*)d_in[3];
    const float* bk    = (const float*)d_in[4];
    const float* Wv    = (const float*)d_in[5];
    const float* bv    = (const float*)d_in[6];
    const float* Wo    = (const float*)d_in[7];
    const float* bo    = (const float*)d_in[8];
    const float* gamma = (const float*)d_in[9];
    float* out = (float*)d_out;

    const int proj_smem = (2 * 256 * 40 + 2 * 64 * 40) * 2;           // 51200 B
    const int attn_smem = (128 * 72 + 2 * 128 * 72 + 2 * 72 * 136) * 2; // 94464 B
    cudaFuncSetAttribute(proj_qkv_kernel, cudaFuncAttributeMaxDynamicSharedMemorySize, proj_smem);
    cudaFuncSetAttribute(proj_out_kernel, cudaFuncAttributeMaxDynamicSharedMemorySize, proj_smem);
    cudaFuncSetAttribute(attn_kernel,     cudaFuncAttributeMaxDynamicSharedMemorySize, attn_smem);

    convert_w_kernel<<<4 * C * C / 256, 256>>>(Wq, Wk, Wv, Wo);
    transpose_x_kernel<<<dim3(SP / 32, C / 32, NB), 256>>>(x);
    proj_qkv_kernel<<<dim3(SP / 256, C / 64, 3 * NB), 256, proj_smem>>>(bq, bk, bv);
    attn_kernel<<<dim3(SP / 128, NB * NH), 256, attn_smem>>>();
    proj_out_kernel<<<dim3(SP / 256, C / 64, NB), 256, proj_smem>>>(x, bo, gamma, out);
}